// round 15
// baseline (speedup 1.0000x reference)
#include <cuda_runtime.h>
#include <math.h>

#define N_NODES 50000
#define N_EDGES 1600000
#define D 128

// ---------------- scratch (static device globals; no allocs allowed) --------
__device__ int   g_cnt[N_NODES];        // in-degree (without self loop)
__device__ int   g_off[N_NODES + 1];    // CSR row offsets (by dst)
__device__ int   g_cur[N_NODES];        // fill cursors
__device__ int   g_csr[N_EDGES];        // src ids grouped by dst
__device__ float g_dis[N_NODES];        // rsqrt(deg)
__device__ float g_bufA[(size_t)N_NODES * D];   // HS1, later HS2
__device__ float g_bufB[(size_t)N_NODES * D];   // x1

// ---------------- CSR build --------------------------------------------------
__global__ void k_zero_cnt() {
    int i = blockIdx.x * blockDim.x + threadIdx.x;
    if (i < N_NODES) g_cnt[i] = 0;
}

__global__ void k_count(const int* __restrict__ dst) {
    int e = blockIdx.x * blockDim.x + threadIdx.x;
    if (e < N_EDGES) atomicAdd(&g_cnt[dst[e]], 1);
}

// single-block exclusive scan over g_cnt -> g_off, g_cur; also dis = rsqrt(1+cnt)
#define SCAN_T 1024
#define SCAN_ITEMS 49   // ceil(50000/1024)
__global__ void __launch_bounds__(SCAN_T) k_scan() {
    __shared__ int s[SCAN_T];
    int t = threadIdx.x;
    int beg = t * SCAN_ITEMS;
    int end = beg + SCAN_ITEMS; if (end > N_NODES) end = N_NODES;
    int sum = 0;
    for (int i = beg; i < end; ++i) sum += g_cnt[i];
    s[t] = sum;
    __syncthreads();
    // Hillis-Steele inclusive scan
    for (int off = 1; off < SCAN_T; off <<= 1) {
        int v = (t >= off) ? s[t - off] : 0;
        __syncthreads();
        s[t] += v;
        __syncthreads();
    }
    int run = (t == 0) ? 0 : s[t - 1];
    for (int i = beg; i < end; ++i) {
        g_off[i] = run;
        g_cur[i] = run;
        int c = g_cnt[i];
        g_dis[i] = rsqrtf((float)(c + 1));
        run += c;
    }
    if (t == SCAN_T - 1) g_off[N_NODES] = s[SCAN_T - 1];
}

__global__ void k_fill(const int* __restrict__ src, const int* __restrict__ dst) {
    int e = blockIdx.x * blockDim.x + threadIdx.x;
    if (e >= N_EDGES) return;
    int d = dst[e];
    int pos = atomicAdd(&g_cur[d], 1);
    g_csr[pos] = src[e];
}

// ---------------- GEMM: HS = (X @ W) * dis[row] ------------------------------
// 128x128 block tile, 256 threads, 8x8 register tile, K chunked by 32.
__global__ void __launch_bounds__(256) k_gemm(
    const float* __restrict__ X, const float* __restrict__ W,
    float* __restrict__ HS)
{
    __shared__ float Ws[32][D];        // 16 KB : Ws[k][col]
    __shared__ float Xs[32][132];      // ~16.5 KB : Xs[k][row], padded

    const int t  = threadIdx.x;
    const int tx = t & 15;    // col group: cols tx*8 .. +7
    const int ty = t >> 4;    // row group: rows ty*8 .. +7
    const int row0 = blockIdx.x * 128;

    float acc[8][8];
#pragma unroll
    for (int r = 0; r < 8; ++r)
#pragma unroll
        for (int c = 0; c < 8; ++c) acc[r][c] = 0.0f;

    for (int kc = 0; kc < 4; ++kc) {
        // W chunk: 32 rows x 128 cols = 1024 float4, 4 per thread
        {
            const float4* Wg = (const float4*)(W + (size_t)kc * 32 * D);
            float4* Wsv = (float4*)(&Ws[0][0]);
#pragma unroll
            for (int i = 0; i < 4; ++i) Wsv[t + i * 256] = Wg[t + i * 256];
        }
        // X chunk transposed: 128 rows x 32 k  -> Xs[k][row]
        {
#pragma unroll
            for (int i = 0; i < 4; ++i) {
                int lin = t + i * 256;      // 0..1023
                int r   = lin >> 3;         // row within tile 0..127
                int c4  = lin & 7;          // float4 within 32-k chunk
                int gr  = row0 + r;
                float4 v = make_float4(0.f, 0.f, 0.f, 0.f);
                if (gr < N_NODES)
                    v = *(const float4*)(X + (size_t)gr * D + kc * 32 + c4 * 4);
                Xs[c4 * 4 + 0][r] = v.x;
                Xs[c4 * 4 + 1][r] = v.y;
                Xs[c4 * 4 + 2][r] = v.z;
                Xs[c4 * 4 + 3][r] = v.w;
            }
        }
        __syncthreads();

#pragma unroll 8
        for (int k = 0; k < 32; ++k) {
            float4 w0 = *(const float4*)(&Ws[k][tx * 8]);
            float4 w1 = *(const float4*)(&Ws[k][tx * 8 + 4]);
            float4 x0 = *(const float4*)(&Xs[k][ty * 8]);
            float4 x1 = *(const float4*)(&Xs[k][ty * 8 + 4]);
            float xv[8] = {x0.x, x0.y, x0.z, x0.w, x1.x, x1.y, x1.z, x1.w};
            float wv[8] = {w0.x, w0.y, w0.z, w0.w, w1.x, w1.y, w1.z, w1.w};
#pragma unroll
            for (int r = 0; r < 8; ++r)
#pragma unroll
                for (int c = 0; c < 8; ++c)
                    acc[r][c] += xv[r] * wv[c];
        }
        __syncthreads();
    }

#pragma unroll
    for (int r = 0; r < 8; ++r) {
        int gr = row0 + ty * 8 + r;
        if (gr < N_NODES) {
            float dis = g_dis[gr];
            float4 o0 = make_float4(acc[r][0] * dis, acc[r][1] * dis,
                                    acc[r][2] * dis, acc[r][3] * dis);
            float4 o1 = make_float4(acc[r][4] * dis, acc[r][5] * dis,
                                    acc[r][6] * dis, acc[r][7] * dis);
            size_t off = (size_t)gr * D + tx * 8;
            *(float4*)(HS + off)     = o0;
            *(float4*)(HS + off + 4) = o1;
        }
    }
}

// ---------------- gather + relu: X1[i] = relu(dis*(HS[i] + sum_in HS[s]) + b)
__global__ void __launch_bounds__(256) k_gather_relu(
    const float* __restrict__ HS, const float* __restrict__ b,
    float* __restrict__ Xout)
{
    int gidx = blockIdx.x * blockDim.x + threadIdx.x;
    int row  = gidx >> 5;
    int lane = gidx & 31;
    if (row >= N_NODES) return;

    const float4* HSv = (const float4*)HS;
    float4 acc = __ldg(&HSv[(size_t)row * 32 + lane]);   // self loop

    int beg = g_off[row], end = g_off[row + 1];
    for (int base = beg; base < end; base += 32) {
        int idx2 = base + lane;
        int eid  = (idx2 < end) ? g_csr[idx2] : 0;
        int cnt  = end - base; if (cnt > 32) cnt = 32;
#pragma unroll 4
        for (int j = 0; j < cnt; ++j) {
            int s = __shfl_sync(0xffffffffu, eid, j);
            float4 v = __ldg(&HSv[(size_t)s * 32 + lane]);
            acc.x += v.x; acc.y += v.y; acc.z += v.z; acc.w += v.w;
        }
    }

    float dis = g_dis[row];
    float4 bb = __ldg(((const float4*)b) + lane);
    float4 o;
    o.x = fmaxf(dis * acc.x + bb.x, 0.f);
    o.y = fmaxf(dis * acc.y + bb.y, 0.f);
    o.z = fmaxf(dis * acc.z + bb.z, 0.f);
    o.w = fmaxf(dis * acc.w + bb.w, 0.f);
    ((float4*)Xout)[(size_t)row * 32 + lane] = o;
}

// ---------------- gather + relu + head: out[i] = sigmoid(relu(...)·hw + hb) --
__global__ void __launch_bounds__(256) k_gather_head(
    const float* __restrict__ HS, const float* __restrict__ b2,
    const float* __restrict__ hw, const float* __restrict__ hb,
    float* __restrict__ out)
{
    int gidx = blockIdx.x * blockDim.x + threadIdx.x;
    int row  = gidx >> 5;
    int lane = gidx & 31;
    if (row >= N_NODES) return;

    const float4* HSv = (const float4*)HS;
    float4 acc = __ldg(&HSv[(size_t)row * 32 + lane]);   // self loop

    int beg = g_off[row], end = g_off[row + 1];
    for (int base = beg; base < end; base += 32) {
        int idx2 = base + lane;
        int eid  = (idx2 < end) ? g_csr[idx2] : 0;
        int cnt  = end - base; if (cnt > 32) cnt = 32;
#pragma unroll 4
        for (int j = 0; j < cnt; ++j) {
            int s = __shfl_sync(0xffffffffu, eid, j);
            float4 v = __ldg(&HSv[(size_t)s * 32 + lane]);
            acc.x += v.x; acc.y += v.y; acc.z += v.z; acc.w += v.w;
        }
    }

    float dis = g_dis[row];
    float4 bb = __ldg(((const float4*)b2) + lane);
    float4 w  = __ldg(((const float4*)hw) + lane);
    float x0 = fmaxf(dis * acc.x + bb.x, 0.f);
    float x1 = fmaxf(dis * acc.y + bb.y, 0.f);
    float x2 = fmaxf(dis * acc.z + bb.z, 0.f);
    float x3 = fmaxf(dis * acc.w + bb.w, 0.f);
    float p = x0 * w.x + x1 * w.y + x2 * w.z + x3 * w.w;
#pragma unroll
    for (int off = 16; off > 0; off >>= 1)
        p += __shfl_down_sync(0xffffffffu, p, off);
    if (lane == 0) {
        float s = p + __ldg(hb);
        out[row] = 1.0f / (1.0f + expf(-s));
    }
}

// ---------------- launch -----------------------------------------------------
extern "C" void kernel_launch(void* const* d_in, const int* in_sizes, int n_in,
                              void* d_out, int out_size)
{
    const int*   edge = (const int*)d_in[0];   // [2, E] int32
    const float* emb  = (const float*)d_in[1];
    const float* W1   = (const float*)d_in[2];
    const float* b1   = (const float*)d_in[3];
    const float* W2   = (const float*)d_in[4];
    const float* b2   = (const float*)d_in[5];
    const float* hw   = (const float*)d_in[6];
    const float* hb   = (const float*)d_in[7];
    float* out = (float*)d_out;

    const int* src = edge;
    const int* dst = edge + N_EDGES;

    float *pA, *pB;
    cudaGetSymbolAddress((void**)&pA, g_bufA);
    cudaGetSymbolAddress((void**)&pB, g_bufB);

    const int NB_N   = (N_NODES + 255) / 256;
    const int NB_E   = (N_EDGES + 255) / 256;
    const int NB_GEM = (N_NODES + 127) / 128;
    const int NB_ROW = (int)(((size_t)N_NODES * 32 + 255) / 256);

    // CSR build (by dst) + norms
    k_zero_cnt<<<NB_N, 256>>>();
    k_count   <<<NB_E, 256>>>(dst);
    k_scan    <<<1, SCAN_T>>>();
    k_fill    <<<NB_E, 256>>>(src, dst);

    // layer 1: HS1 -> bufA; x1 -> bufB
    k_gemm       <<<NB_GEM, 256>>>(emb, W1, pA);
    k_gather_relu<<<NB_ROW, 256>>>(pA, b1, pB);

    // layer 2: HS2 -> bufA; fused gather + head -> out
    k_gemm       <<<NB_GEM, 256>>>(pB, W2, pA);
    k_gather_head<<<NB_ROW, 256>>>(pA, b2, hw, hb, out);
}

// round 16
// speedup vs baseline: 1.0987x; 1.0987x over previous
#include <cuda_runtime.h>
#include <cuda_fp16.h>
#include <math.h>

#define N_NODES 50000
#define N_EDGES 1600000
#define D 128

// ---------------- scratch (static device globals; no allocs allowed) --------
__device__ int    g_cnt[N_NODES];        // in-degree (without self loop)
__device__ int    g_off[N_NODES + 1];    // CSR row offsets (by dst)
__device__ int    g_cur[N_NODES];        // fill cursors
__device__ int    g_csr[N_EDGES];        // src ids grouped by dst
__device__ float  g_dis[N_NODES];        // rsqrt(deg)
__device__ __half g_hs[(size_t)N_NODES * D];   // HS messages (fp16)
__device__ float  g_x1[(size_t)N_NODES * D];   // layer-1 output (fp32)

// ---------------- CSR build --------------------------------------------------
__global__ void k_zero_cnt() {
    int i = blockIdx.x * blockDim.x + threadIdx.x;
    if (i < N_NODES) g_cnt[i] = 0;
}

// 4 edges per thread: int4 load + 4 independent atomics (MLP=4)
__global__ void k_count(const int* __restrict__ dst) {
    int e0 = (blockIdx.x * blockDim.x + threadIdx.x) * 4;
    if (e0 >= N_EDGES) return;
    int4 d4 = *(const int4*)(dst + e0);     // N_EDGES % 4 == 0
    atomicAdd(&g_cnt[d4.x], 1);
    atomicAdd(&g_cnt[d4.y], 1);
    atomicAdd(&g_cnt[d4.z], 1);
    atomicAdd(&g_cnt[d4.w], 1);
}

// single-block exclusive scan over g_cnt -> g_off, g_cur; also dis = rsqrt(1+cnt)
#define SCAN_T 1024
#define SCAN_ITEMS 49   // ceil(50000/1024)
__global__ void __launch_bounds__(SCAN_T) k_scan() {
    __shared__ int s[SCAN_T];
    int t = threadIdx.x;
    int beg = t * SCAN_ITEMS;
    int end = beg + SCAN_ITEMS; if (end > N_NODES) end = N_NODES;
    int sum = 0;
    for (int i = beg; i < end; ++i) sum += g_cnt[i];
    s[t] = sum;
    __syncthreads();
    for (int off = 1; off < SCAN_T; off <<= 1) {
        int v = (t >= off) ? s[t - off] : 0;
        __syncthreads();
        s[t] += v;
        __syncthreads();
    }
    int run = (t == 0) ? 0 : s[t - 1];
    for (int i = beg; i < end; ++i) {
        g_off[i] = run;
        g_cur[i] = run;
        int c = g_cnt[i];
        g_dis[i] = rsqrtf((float)(c + 1));
        run += c;
    }
    if (t == SCAN_T - 1) g_off[N_NODES] = s[SCAN_T - 1];
}

// 4 edges per thread: 4 independent returning atomics in flight
__global__ void k_fill(const int* __restrict__ src, const int* __restrict__ dst) {
    int e0 = (blockIdx.x * blockDim.x + threadIdx.x) * 4;
    if (e0 >= N_EDGES) return;
    int4 d4 = *(const int4*)(dst + e0);
    int4 s4 = *(const int4*)(src + e0);
    int p0 = atomicAdd(&g_cur[d4.x], 1);
    int p1 = atomicAdd(&g_cur[d4.y], 1);
    int p2 = atomicAdd(&g_cur[d4.z], 1);
    int p3 = atomicAdd(&g_cur[d4.w], 1);
    g_csr[p0] = s4.x;
    g_csr[p1] = s4.y;
    g_csr[p2] = s4.z;
    g_csr[p3] = s4.w;
}

// ---------------- GEMM: HS = fp16((X @ W) * dis[row]) ------------------------
// 128x128 block tile, 256 threads, 8x8 register tile, K chunked by 32.
__global__ void __launch_bounds__(256) k_gemm(
    const float* __restrict__ X, const float* __restrict__ W,
    __half* __restrict__ HS)
{
    __shared__ float Ws[32][D];        // 16 KB : Ws[k][col]
    __shared__ float Xs[32][132];      // ~16.5 KB : Xs[k][row], padded

    const int t  = threadIdx.x;
    const int tx = t & 15;    // col group: cols tx*8 .. +7
    const int ty = t >> 4;    // row group: rows ty*8 .. +7
    const int row0 = blockIdx.x * 128;

    float acc[8][8];
#pragma unroll
    for (int r = 0; r < 8; ++r)
#pragma unroll
        for (int c = 0; c < 8; ++c) acc[r][c] = 0.0f;

    for (int kc = 0; kc < 4; ++kc) {
        {
            const float4* Wg = (const float4*)(W + (size_t)kc * 32 * D);
            float4* Wsv = (float4*)(&Ws[0][0]);
#pragma unroll
            for (int i = 0; i < 4; ++i) Wsv[t + i * 256] = Wg[t + i * 256];
        }
        {
#pragma unroll
            for (int i = 0; i < 4; ++i) {
                int lin = t + i * 256;      // 0..1023
                int r   = lin >> 3;         // row within tile 0..127
                int c4  = lin & 7;          // float4 within 32-k chunk
                int gr  = row0 + r;
                float4 v = make_float4(0.f, 0.f, 0.f, 0.f);
                if (gr < N_NODES)
                    v = *(const float4*)(X + (size_t)gr * D + kc * 32 + c4 * 4);
                Xs[c4 * 4 + 0][r] = v.x;
                Xs[c4 * 4 + 1][r] = v.y;
                Xs[c4 * 4 + 2][r] = v.z;
                Xs[c4 * 4 + 3][r] = v.w;
            }
        }
        __syncthreads();

#pragma unroll 8
        for (int k = 0; k < 32; ++k) {
            float4 w0 = *(const float4*)(&Ws[k][tx * 8]);
            float4 w1 = *(const float4*)(&Ws[k][tx * 8 + 4]);
            float4 x0 = *(const float4*)(&Xs[k][ty * 8]);
            float4 x1 = *(const float4*)(&Xs[k][ty * 8 + 4]);
            float xv[8] = {x0.x, x0.y, x0.z, x0.w, x1.x, x1.y, x1.z, x1.w};
            float wv[8] = {w0.x, w0.y, w0.z, w0.w, w1.x, w1.y, w1.z, w1.w};
#pragma unroll
            for (int r = 0; r < 8; ++r)
#pragma unroll
                for (int c = 0; c < 8; ++c)
                    acc[r][c] += xv[r] * wv[c];
        }
        __syncthreads();
    }

#pragma unroll
    for (int r = 0; r < 8; ++r) {
        int gr = row0 + ty * 8 + r;
        if (gr < N_NODES) {
            float dis = g_dis[gr];
            __half2 h01 = __floats2half2_rn(acc[r][0] * dis, acc[r][1] * dis);
            __half2 h23 = __floats2half2_rn(acc[r][2] * dis, acc[r][3] * dis);
            __half2 h45 = __floats2half2_rn(acc[r][4] * dis, acc[r][5] * dis);
            __half2 h67 = __floats2half2_rn(acc[r][6] * dis, acc[r][7] * dis);
            uint4 pk;
            pk.x = *reinterpret_cast<unsigned*>(&h01);
            pk.y = *reinterpret_cast<unsigned*>(&h23);
            pk.z = *reinterpret_cast<unsigned*>(&h45);
            pk.w = *reinterpret_cast<unsigned*>(&h67);
            *(uint4*)(HS + (size_t)gr * D + tx * 8) = pk;   // 16B aligned
        }
    }
}

// helper: accumulate 4 halves (uint2) into float4
__device__ __forceinline__ void acc_h4(float4& acc, uint2 u) {
    __half2 h0 = *reinterpret_cast<__half2*>(&u.x);
    __half2 h1 = *reinterpret_cast<__half2*>(&u.y);
    float2 f0 = __half22float2(h0);
    float2 f1 = __half22float2(h1);
    acc.x += f0.x; acc.y += f0.y; acc.z += f1.x; acc.w += f1.y;
}

// ---------------- gather + relu: X1[i] = relu(dis*(HS[i] + sum_in HS[s]) + b)
__global__ void __launch_bounds__(256) k_gather_relu(
    const __half* __restrict__ HS, const float* __restrict__ b,
    float* __restrict__ Xout)
{
    int gidx = blockIdx.x * blockDim.x + threadIdx.x;
    int row  = gidx >> 5;
    int lane = gidx & 31;
    if (row >= N_NODES) return;

    const uint2* H2 = (const uint2*)HS;   // 4 halves per uint2; 32 per row
    float4 acc = make_float4(0.f, 0.f, 0.f, 0.f);
    acc_h4(acc, __ldg(&H2[(size_t)row * 32 + lane]));   // self loop

    int beg = g_off[row], end = g_off[row + 1];
    for (int base = beg; base < end; base += 32) {
        int idx2 = base + lane;
        int eid  = (idx2 < end) ? g_csr[idx2] : 0;
        int cnt  = end - base; if (cnt > 32) cnt = 32;
#pragma unroll 4
        for (int j = 0; j < cnt; ++j) {
            int s = __shfl_sync(0xffffffffu, eid, j);
            acc_h4(acc, __ldg(&H2[(size_t)s * 32 + lane]));
        }
    }

    float dis = g_dis[row];
    float4 bb = __ldg(((const float4*)b) + lane);
    float4 o;
    o.x = fmaxf(dis * acc.x + bb.x, 0.f);
    o.y = fmaxf(dis * acc.y + bb.y, 0.f);
    o.z = fmaxf(dis * acc.z + bb.z, 0.f);
    o.w = fmaxf(dis * acc.w + bb.w, 0.f);
    ((float4*)Xout)[(size_t)row * 32 + lane] = o;
}

// ---------------- gather + relu + head: out[i] = sigmoid(relu(...)·hw + hb) --
__global__ void __launch_bounds__(256) k_gather_head(
    const __half* __restrict__ HS, const float* __restrict__ b2,
    const float* __restrict__ hw, const float* __restrict__ hb,
    float* __restrict__ out)
{
    int gidx = blockIdx.x * blockDim.x + threadIdx.x;
    int row  = gidx >> 5;
    int lane = gidx & 31;
    if (row >= N_NODES) return;

    const uint2* H2 = (const uint2*)HS;
    float4 acc = make_float4(0.f, 0.f, 0.f, 0.f);
    acc_h4(acc, __ldg(&H2[(size_t)row * 32 + lane]));   // self loop

    int beg = g_off[row], end = g_off[row + 1];
    for (int base = beg; base < end; base += 32) {
        int idx2 = base + lane;
        int eid  = (idx2 < end) ? g_csr[idx2] : 0;
        int cnt  = end - base; if (cnt > 32) cnt = 32;
#pragma unroll 4
        for (int j = 0; j < cnt; ++j) {
            int s = __shfl_sync(0xffffffffu, eid, j);
            acc_h4(acc, __ldg(&H2[(size_t)s * 32 + lane]));
        }
    }

    float dis = g_dis[row];
    float4 bb = __ldg(((const float4*)b2) + lane);
    float4 w  = __ldg(((const float4*)hw) + lane);
    float x0 = fmaxf(dis * acc.x + bb.x, 0.f);
    float x1 = fmaxf(dis * acc.y + bb.y, 0.f);
    float x2 = fmaxf(dis * acc.z + bb.z, 0.f);
    float x3 = fmaxf(dis * acc.w + bb.w, 0.f);
    float p = x0 * w.x + x1 * w.y + x2 * w.z + x3 * w.w;
#pragma unroll
    for (int off = 16; off > 0; off >>= 1)
        p += __shfl_down_sync(0xffffffffu, p, off);
    if (lane == 0) {
        float s = p + __ldg(hb);
        out[row] = 1.0f / (1.0f + expf(-s));
    }
}

// ---------------- launch -----------------------------------------------------
extern "C" void kernel_launch(void* const* d_in, const int* in_sizes, int n_in,
                              void* d_out, int out_size)
{
    const int*   edge = (const int*)d_in[0];   // [2, E] int32
    const float* emb  = (const float*)d_in[1];
    const float* W1   = (const float*)d_in[2];
    const float* b1   = (const float*)d_in[3];
    const float* W2   = (const float*)d_in[4];
    const float* b2   = (const float*)d_in[5];
    const float* hw   = (const float*)d_in[6];
    const float* hb   = (const float*)d_in[7];
    float* out = (float*)d_out;

    const int* src = edge;
    const int* dst = edge + N_EDGES;

    __half* pH;
    float*  pX1;
    cudaGetSymbolAddress((void**)&pH,  g_hs);
    cudaGetSymbolAddress((void**)&pX1, g_x1);

    const int NB_N   = (N_NODES + 255) / 256;
    const int NB_E4  = (N_EDGES / 4 + 255) / 256;
    const int NB_GEM = (N_NODES + 127) / 128;
    const int NB_ROW = (int)(((size_t)N_NODES * 32 + 255) / 256);

    // CSR build (by dst) + norms
    k_zero_cnt<<<NB_N, 256>>>();
    k_count   <<<NB_E4, 256>>>(dst);
    k_scan    <<<1, SCAN_T>>>();
    k_fill    <<<NB_E4, 256>>>(src, dst);

    // layer 1: HS1 (fp16) -> g_hs; x1 -> g_x1
    k_gemm       <<<NB_GEM, 256>>>(emb, W1, pH);
    k_gather_relu<<<NB_ROW, 256>>>(pH, b1, pX1);

    // layer 2: HS2 (fp16) -> g_hs; fused gather + head -> out
    k_gemm       <<<NB_GEM, 256>>>(pX1, W2, pH);
    k_gather_head<<<NB_ROW, 256>>>(pH, b2, hw, hb, out);
}

// round 17
// speedup vs baseline: 1.1001x; 1.0013x over previous
#include <cuda_runtime.h>
#include <cuda_fp16.h>
#include <math.h>

#define N_NODES 50000
#define N_EDGES 1600000
#define D 128

// ---------------- scratch (static device globals; no allocs allowed) --------
__device__ int    g_cnt[N_NODES];        // in-degree (without self loop)
__device__ int    g_off[N_NODES + 1];    // CSR row offsets (by dst)
__device__ int    g_cur[N_NODES];        // fill cursors
__device__ int    g_csr[N_EDGES];        // src ids grouped by dst
__device__ float  g_dis[N_NODES];        // rsqrt(deg)
__device__ __half g_hs[(size_t)N_NODES * D];   // HS messages (fp16)
__device__ float  g_x1[(size_t)N_NODES * D];   // layer-1 output (fp32)

// ---------------- CSR build --------------------------------------------------
__global__ void k_zero_cnt() {
    int i = blockIdx.x * blockDim.x + threadIdx.x;
    if (i < N_NODES) g_cnt[i] = 0;
}

// 4 edges per thread: int4 load + 4 independent atomics (MLP=4)
__global__ void k_count(const int* __restrict__ dst) {
    int e0 = (blockIdx.x * blockDim.x + threadIdx.x) * 4;
    if (e0 >= N_EDGES) return;
    int4 d4 = *(const int4*)(dst + e0);     // N_EDGES % 4 == 0
    atomicAdd(&g_cnt[d4.x], 1);
    atomicAdd(&g_cnt[d4.y], 1);
    atomicAdd(&g_cnt[d4.z], 1);
    atomicAdd(&g_cnt[d4.w], 1);
}

// single-block exclusive scan over g_cnt -> g_off, g_cur; also dis = rsqrt(1+cnt)
#define SCAN_T 1024
#define SCAN_ITEMS 49   // ceil(50000/1024)
__global__ void __launch_bounds__(SCAN_T) k_scan() {
    __shared__ int s[SCAN_T];
    int t = threadIdx.x;
    int beg = t * SCAN_ITEMS;
    int end = beg + SCAN_ITEMS; if (end > N_NODES) end = N_NODES;
    int sum = 0;
    for (int i = beg; i < end; ++i) sum += g_cnt[i];
    s[t] = sum;
    __syncthreads();
    for (int off = 1; off < SCAN_T; off <<= 1) {
        int v = (t >= off) ? s[t - off] : 0;
        __syncthreads();
        s[t] += v;
        __syncthreads();
    }
    int run = (t == 0) ? 0 : s[t - 1];
    for (int i = beg; i < end; ++i) {
        g_off[i] = run;
        g_cur[i] = run;
        int c = g_cnt[i];
        g_dis[i] = rsqrtf((float)(c + 1));
        run += c;
    }
    if (t == SCAN_T - 1) g_off[N_NODES] = s[SCAN_T - 1];
}

// 4 edges per thread: 4 independent returning atomics in flight
__global__ void k_fill(const int* __restrict__ src, const int* __restrict__ dst) {
    int e0 = (blockIdx.x * blockDim.x + threadIdx.x) * 4;
    if (e0 >= N_EDGES) return;
    int4 d4 = *(const int4*)(dst + e0);
    int4 s4 = *(const int4*)(src + e0);
    int p0 = atomicAdd(&g_cur[d4.x], 1);
    int p1 = atomicAdd(&g_cur[d4.y], 1);
    int p2 = atomicAdd(&g_cur[d4.z], 1);
    int p3 = atomicAdd(&g_cur[d4.w], 1);
    g_csr[p0] = s4.x;
    g_csr[p1] = s4.y;
    g_csr[p2] = s4.z;
    g_csr[p3] = s4.w;
}

// ---------------- GEMM: HS = fp16((X @ W) * dis[row]) ------------------------
// 128x128 block tile, 256 threads, 8x8 register tile, K chunked by 32.
__global__ void __launch_bounds__(256) k_gemm(
    const float* __restrict__ X, const float* __restrict__ W,
    __half* __restrict__ HS)
{
    __shared__ float Ws[32][D];        // 16 KB : Ws[k][col]
    __shared__ float Xs[32][132];      // ~16.5 KB : Xs[k][row], padded

    const int t  = threadIdx.x;
    const int tx = t & 15;    // col group: cols tx*8 .. +7
    const int ty = t >> 4;    // row group: rows ty*8 .. +7
    const int row0 = blockIdx.x * 128;

    float acc[8][8];
#pragma unroll
    for (int r = 0; r < 8; ++r)
#pragma unroll
        for (int c = 0; c < 8; ++c) acc[r][c] = 0.0f;

    for (int kc = 0; kc < 4; ++kc) {
        {
            const float4* Wg = (const float4*)(W + (size_t)kc * 32 * D);
            float4* Wsv = (float4*)(&Ws[0][0]);
#pragma unroll
            for (int i = 0; i < 4; ++i) Wsv[t + i * 256] = Wg[t + i * 256];
        }
        {
#pragma unroll
            for (int i = 0; i < 4; ++i) {
                int lin = t + i * 256;      // 0..1023
                int r   = lin >> 3;         // row within tile 0..127
                int c4  = lin & 7;          // float4 within 32-k chunk
                int gr  = row0 + r;
                float4 v = make_float4(0.f, 0.f, 0.f, 0.f);
                if (gr < N_NODES)
                    v = *(const float4*)(X + (size_t)gr * D + kc * 32 + c4 * 4);
                Xs[c4 * 4 + 0][r] = v.x;
                Xs[c4 * 4 + 1][r] = v.y;
                Xs[c4 * 4 + 2][r] = v.z;
                Xs[c4 * 4 + 3][r] = v.w;
            }
        }
        __syncthreads();

#pragma unroll 8
        for (int k = 0; k < 32; ++k) {
            float4 w0 = *(const float4*)(&Ws[k][tx * 8]);
            float4 w1 = *(const float4*)(&Ws[k][tx * 8 + 4]);
            float4 x0 = *(const float4*)(&Xs[k][ty * 8]);
            float4 x1 = *(const float4*)(&Xs[k][ty * 8 + 4]);
            float xv[8] = {x0.x, x0.y, x0.z, x0.w, x1.x, x1.y, x1.z, x1.w};
            float wv[8] = {w0.x, w0.y, w0.z, w0.w, w1.x, w1.y, w1.z, w1.w};
#pragma unroll
            for (int r = 0; r < 8; ++r)
#pragma unroll
                for (int c = 0; c < 8; ++c)
                    acc[r][c] += xv[r] * wv[c];
        }
        __syncthreads();
    }

#pragma unroll
    for (int r = 0; r < 8; ++r) {
        int gr = row0 + ty * 8 + r;
        if (gr < N_NODES) {
            float dis = g_dis[gr];
            __half2 h01 = __floats2half2_rn(acc[r][0] * dis, acc[r][1] * dis);
            __half2 h23 = __floats2half2_rn(acc[r][2] * dis, acc[r][3] * dis);
            __half2 h45 = __floats2half2_rn(acc[r][4] * dis, acc[r][5] * dis);
            __half2 h67 = __floats2half2_rn(acc[r][6] * dis, acc[r][7] * dis);
            uint4 pk;
            pk.x = *reinterpret_cast<unsigned*>(&h01);
            pk.y = *reinterpret_cast<unsigned*>(&h23);
            pk.z = *reinterpret_cast<unsigned*>(&h45);
            pk.w = *reinterpret_cast<unsigned*>(&h67);
            *(uint4*)(HS + (size_t)gr * D + tx * 8) = pk;   // 16B aligned
        }
    }
}

// helper: accumulate 4 halves (uint2) into float4
__device__ __forceinline__ void acc_h4(float4& acc, uint2 u) {
    __half2 h0 = *reinterpret_cast<__half2*>(&u.x);
    __half2 h1 = *reinterpret_cast<__half2*>(&u.y);
    float2 f0 = __half22float2(h0);
    float2 f1 = __half22float2(h1);
    acc.x += f0.x; acc.y += f0.y; acc.z += f1.x; acc.w += f1.y;
}

// ---------------- gather + relu: X1[i] = relu(dis*(HS[i] + sum_in HS[s]) + b)
__global__ void __launch_bounds__(256) k_gather_relu(
    const __half* __restrict__ HS, const float* __restrict__ b,
    float* __restrict__ Xout)
{
    int gidx = blockIdx.x * blockDim.x + threadIdx.x;
    int row  = gidx >> 5;
    int lane = gidx & 31;
    if (row >= N_NODES) return;

    const uint2* H2 = (const uint2*)HS;   // 4 halves per uint2; 32 per row
    float4 acc = make_float4(0.f, 0.f, 0.f, 0.f);
    acc_h4(acc, __ldg(&H2[(size_t)row * 32 + lane]));   // self loop

    int beg = g_off[row], end = g_off[row + 1];
    for (int base = beg; base < end; base += 32) {
        int idx2 = base + lane;
        int eid  = (idx2 < end) ? g_csr[idx2] : 0;
        int cnt  = end - base; if (cnt > 32) cnt = 32;
#pragma unroll 4
        for (int j = 0; j < cnt; ++j) {
            int s = __shfl_sync(0xffffffffu, eid, j);
            acc_h4(acc, __ldg(&H2[(size_t)s * 32 + lane]));
        }
    }

    float dis = g_dis[row];
    float4 bb = __ldg(((const float4*)b) + lane);
    float4 o;
    o.x = fmaxf(dis * acc.x + bb.x, 0.f);
    o.y = fmaxf(dis * acc.y + bb.y, 0.f);
    o.z = fmaxf(dis * acc.z + bb.z, 0.f);
    o.w = fmaxf(dis * acc.w + bb.w, 0.f);
    ((float4*)Xout)[(size_t)row * 32 + lane] = o;
}

// ---------------- gather + relu + head: out[i] = sigmoid(relu(...)·hw + hb) --
__global__ void __launch_bounds__(256) k_gather_head(
    const __half* __restrict__ HS, const float* __restrict__ b2,
    const float* __restrict__ hw, const float* __restrict__ hb,
    float* __restrict__ out)
{
    int gidx = blockIdx.x * blockDim.x + threadIdx.x;
    int row  = gidx >> 5;
    int lane = gidx & 31;
    if (row >= N_NODES) return;

    const uint2* H2 = (const uint2*)HS;
    float4 acc = make_float4(0.f, 0.f, 0.f, 0.f);
    acc_h4(acc, __ldg(&H2[(size_t)row * 32 + lane]));   // self loop

    int beg = g_off[row], end = g_off[row + 1];
    for (int base = beg; base < end; base += 32) {
        int idx2 = base + lane;
        int eid  = (idx2 < end) ? g_csr[idx2] : 0;
        int cnt  = end - base; if (cnt > 32) cnt = 32;
#pragma unroll 4
        for (int j = 0; j < cnt; ++j) {
            int s = __shfl_sync(0xffffffffu, eid, j);
            acc_h4(acc, __ldg(&H2[(size_t)s * 32 + lane]));
        }
    }

    float dis = g_dis[row];
    float4 bb = __ldg(((const float4*)b2) + lane);
    float4 w  = __ldg(((const float4*)hw) + lane);
    float x0 = fmaxf(dis * acc.x + bb.x, 0.f);
    float x1 = fmaxf(dis * acc.y + bb.y, 0.f);
    float x2 = fmaxf(dis * acc.z + bb.z, 0.f);
    float x3 = fmaxf(dis * acc.w + bb.w, 0.f);
    float p = x0 * w.x + x1 * w.y + x2 * w.z + x3 * w.w;
#pragma unroll
    for (int off = 16; off > 0; off >>= 1)
        p += __shfl_down_sync(0xffffffffu, p, off);
    if (lane == 0) {
        float s = p + __ldg(hb);
        out[row] = 1.0f / (1.0f + expf(-s));
    }
}

// ---------------- launch -----------------------------------------------------
extern "C" void kernel_launch(void* const* d_in, const int* in_sizes, int n_in,
                              void* d_out, int out_size)
{
    const int*   edge = (const int*)d_in[0];   // [2, E] int32
    const float* emb  = (const float*)d_in[1];
    const float* W1   = (const float*)d_in[2];
    const float* b1   = (const float*)d_in[3];
    const float* W2   = (const float*)d_in[4];
    const float* b2   = (const float*)d_in[5];
    const float* hw   = (const float*)d_in[6];
    const float* hb   = (const float*)d_in[7];
    float* out = (float*)d_out;

    const int* src = edge;
    const int* dst = edge + N_EDGES;

    __half* pH;
    float*  pX1;
    cudaGetSymbolAddress((void**)&pH,  g_hs);
    cudaGetSymbolAddress((void**)&pX1, g_x1);

    const int NB_N   = (N_NODES + 255) / 256;
    const int NB_E4  = (N_EDGES / 4 + 255) / 256;
    const int NB_GEM = (N_NODES + 127) / 128;
    const int NB_ROW = (int)(((size_t)N_NODES * 32 + 255) / 256);

    // CSR build (by dst) + norms
    k_zero_cnt<<<NB_N, 256>>>();
    k_count   <<<NB_E4, 256>>>(dst);
    k_scan    <<<1, SCAN_T>>>();
    k_fill    <<<NB_E4, 256>>>(src, dst);

    // layer 1: HS1 (fp16) -> g_hs; x1 -> g_x1
    k_gemm       <<<NB_GEM, 256>>>(emb, W1, pH);
    k_gather_relu<<<NB_ROW, 256>>>(pH, b1, pX1);

    // layer 2: HS2 (fp16) -> g_hs; fused gather + head -> out
    k_gemm       <<<NB_GEM, 256>>>(pX1, W2, pH);
    k_gather_head<<<NB_ROW, 256>>>(pH, b2, hw, hb, out);
}